// round 11
// baseline (speedup 1.0000x reference)
#include <cuda_runtime.h>
#include <cuda_bf16.h>
#include <cstdint>

#define BB 2048
#define CC 1024
#define FF 128
#define NIT 10
#define NBLK 128              // sink blocks: single wave, barrier-safe
#define ROWS_S (BB/NBLK)      // 16 rows per sink block
#define BANKS 4

// Scratch (no allocs allowed -> device globals)
__device__ float    g_M[BB*CC];             // M[b][j] = ue_b . item_emb[j]
__device__ float    g_cs[NIT+1][CC][BANKS]; // colsum partials, bank-minor for LDG.128
__device__ float    g_sumDp[256];           // per-gemm-block sumD partials (overwrite)
__device__ unsigned g_bar[16];              // grid-barrier counters

// ---------------- tensor-core GEMM + sumD + zeroing --------------------------
// grid (16,16): block tile 128(m) x 64(n), k=128 single stage.
// Loads fp32 (gather for A), converts bf16 in-register. Also: zeroes colsum
// banks/barriers, and computes per-block D partial sums (D loads issued first
// so their latency hides under the MMA loop).
__device__ __forceinline__ void ldmx4(uint32_t& r0, uint32_t& r1, uint32_t& r2, uint32_t& r3,
                                      uint32_t addr) {
    asm volatile("ldmatrix.sync.aligned.m8n8.x4.shared.b16 {%0,%1,%2,%3}, [%4];"
                 : "=r"(r0), "=r"(r1), "=r"(r2), "=r"(r3) : "r"(addr));
}

__device__ __forceinline__ uint32_t bf2u(float x, float y) {
    __nv_bfloat162 h = __floats2bfloat162_rn(x, y);
    return *reinterpret_cast<uint32_t*>(&h);
}

__global__ void __launch_bounds__(256) k_gemm_mma(const int* __restrict__ users,
                                                  const float* __restrict__ user_emb,
                                                  const float* __restrict__ item_emb,
                                                  const float* __restrict__ D) {
    __shared__ __align__(16) char smem[49152];   // A: 32KB (128x256B), B: 16KB (64x256B)
    char* sA = smem;
    char* sB = smem + 32768;
    uint32_t sA0 = (uint32_t)__cvta_generic_to_shared(sA);
    uint32_t sB0 = (uint32_t)__cvta_generic_to_shared(sB);

    int t = threadIdx.x;
    int blin = blockIdx.y * gridDim.x + blockIdx.x;
    int r0b = blockIdx.y * 128, c0b = blockIdx.x * 64;

    // ---- D partial loads (consumed at the very end; latency hidden) ----
    float4 dv[8];
    #pragma unroll
    for (int k = 0; k < 8; k++)
        dv[k] = ((const float4*)D)[blin*2048 + t + k*256];

    // ---- zero accumulators (45072 words over 65536 threads) ----
    {
        int lin = blin * 256 + t;
        if (lin < (NIT+1)*CC*BANKS) (&g_cs[0][0][0])[lin] = 0.f;
        if (lin < 16) g_bar[lin] = 0u;
    }

    // ---- A tile: gather rows via users, fp32 -> bf16, swizzled smem ----
    #pragma unroll
    for (int l = 0; l < 16; l++) {
        int id = t + l*256;              // 4096 uint4 (128 rows x 32)
        int r = id >> 5, c = id & 31;
        int urow = users[r0b + r];
        uint4 vi = ((const uint4*)(user_emb + (size_t)urow*FF))[c];
        float4 v = *reinterpret_cast<float4*>(&vi);
        uint2 st = make_uint2(bf2u(v.x, v.y), bf2u(v.z, v.w));
        *(uint2*)(sA + r*256 + (((c>>1) ^ (r & 7)) << 4) + ((c & 1) << 3)) = st;
    }
    // ---- B tile: fp32 -> bf16 ----
    #pragma unroll
    for (int l = 0; l < 8; l++) {
        int id = t + l*256;              // 2048 uint4 (64 rows x 32)
        int r = id >> 5, c = id & 31;
        uint4 vi = ((const uint4*)(item_emb + (size_t)(c0b + r)*FF))[c];
        float4 v = *reinterpret_cast<float4*>(&vi);
        uint2 st = make_uint2(bf2u(v.x, v.y), bf2u(v.z, v.w));
        *(uint2*)(sB + r*256 + (((c>>1) ^ (r & 7)) << 4) + ((c & 1) << 3)) = st;
    }
    __syncthreads();

    int wid  = t >> 5, lane = t & 31;
    int wm = wid & 3, wn = wid >> 2;
    int jm = lane >> 3, rr = lane & 7;

    float c[2][4][4];
    #pragma unroll
    for (int mi = 0; mi < 2; mi++)
        #pragma unroll
        for (int nj = 0; nj < 4; nj++)
            #pragma unroll
            for (int e = 0; e < 4; e++) c[mi][nj][e] = 0.f;

    #pragma unroll
    for (int kk = 0; kk < 8; kk++) {
        uint32_t a[2][4];
        #pragma unroll
        for (int mi = 0; mi < 2; mi++) {
            int row = wm*32 + mi*16 + (jm & 1)*8 + rr;
            int ch  = 2*kk + (jm >> 1);
            ldmx4(a[mi][0], a[mi][1], a[mi][2], a[mi][3],
                  sA0 + row*256 + ((ch ^ (row & 7)) << 4));
        }
        uint32_t b[4][2];
        #pragma unroll
        for (int q = 0; q < 2; q++) {
            int row = wn*32 + q*16 + (jm >> 1)*8 + rr;
            int ch  = 2*kk + (jm & 1);
            uint32_t r0_, r1_, r2_, r3_;
            ldmx4(r0_, r1_, r2_, r3_, sB0 + row*256 + ((ch ^ (row & 7)) << 4));
            b[q*2][0] = r0_; b[q*2][1] = r1_;
            b[q*2+1][0] = r2_; b[q*2+1][1] = r3_;
        }
        #pragma unroll
        for (int mi = 0; mi < 2; mi++)
            #pragma unroll
            for (int nj = 0; nj < 4; nj++) {
                asm volatile(
                    "mma.sync.aligned.m16n8k16.row.col.f32.bf16.bf16.f32 "
                    "{%0,%1,%2,%3}, {%4,%5,%6,%7}, {%8,%9}, {%0,%1,%2,%3};"
                    : "+f"(c[mi][nj][0]), "+f"(c[mi][nj][1]),
                      "+f"(c[mi][nj][2]), "+f"(c[mi][nj][3])
                    : "r"(a[mi][0]), "r"(a[mi][1]), "r"(a[mi][2]), "r"(a[mi][3]),
                      "r"(b[nj][0]), "r"(b[nj][1]));
            }
    }

    int g = lane >> 2, tc = lane & 3;
    #pragma unroll
    for (int mi = 0; mi < 2; mi++) {
        int row = r0b + wm*32 + mi*16 + g;
        #pragma unroll
        for (int nj = 0; nj < 4; nj++) {
            int col = c0b + wn*32 + nj*8 + tc*2;
            *(float2*)&g_M[(size_t)row*CC + col]     = make_float2(c[mi][nj][0], c[mi][nj][1]);
            *(float2*)&g_M[(size_t)(row+8)*CC + col] = make_float2(c[mi][nj][2], c[mi][nj][3]);
        }
    }

    // ---- D partial sum -> g_sumDp[blin] (plain overwrite, replay-safe) ----
    float s = 0.f;
    #pragma unroll
    for (int k = 0; k < 8; k++)
        s += (dv[k].x + dv[k].y) + (dv[k].z + dv[k].w);
    __syncthreads();                 // smem A/B reads all done; reuse as reducer
    float* red = (float*)smem;
    red[t] = s; __syncthreads();
    for (int o = 128; o > 0; o >>= 1) { if (t < o) red[t] += red[t+o]; __syncthreads(); }
    if (t == 0) g_sumDp[blin] = red[0];
}

// ------- grid barrier: red.release arrival + ld.acquire spin (no MEMBAR) -------
__device__ __forceinline__ void grid_barrier(int id) {
    __syncthreads();
    if (threadIdx.x == 0) {
        unsigned* p = &g_bar[id];
        asm volatile("red.release.gpu.global.add.u32 [%0], %1;"
                     :: "l"(p), "r"(1u) : "memory");
        unsigned v;
        do {
            asm volatile("ld.acquire.gpu.global.u32 %0, [%1];"
                         : "=r"(v) : "l"(p) : "memory");
        } while (v < (unsigned)NBLK);
    }
    __syncthreads();
}

// ------- fused sink: sumD-reduce + K build + iter1..10 + final P --------------
// 128 blocks x 512 threads, 16 rows/block; thread t owns cols 2t,2t+1.
__global__ void __launch_bounds__(512, 1)
k_sink(const int* __restrict__ items, const float* __restrict__ D,
       const float* __restrict__ capacities, float* __restrict__ out) {
    __shared__ __align__(16) float sbuf[8*CC];   // 32 KB: mrows stage / rowsum scratch
    __shared__ float su[ROWS_S];
    int t   = threadIdx.x;
    int bid = blockIdx.x;
    int b0  = bid * ROWS_S;
    int sb  = bid & (BANKS-1);
    int w = t >> 5, l = t & 31;

    // ---- sumD: reduce 256 per-gemm-block partials (local, no global barrier) ----
    if (t < 128) sbuf[t] = g_sumDp[t] + g_sumDp[t + 128];
    __syncthreads();
    for (int o = 64; o > 0; o >>= 1) { if (t < o) sbuf[t] += sbuf[t+o]; __syncthreads(); }
    float inv_mean = (float)(BB*CC) / sbuf[0];
    __syncthreads();

    // ---- build K in registers: two 8-row passes, D/items inline ----
    float2 kv[ROWS_S];
    #pragma unroll
    for (int half = 0; half < 2; half++) {
        int2   it2[8];
        float2 dd[8];
        #pragma unroll
        for (int r = 0; r < 8; r++)
            ((float2*)&sbuf[r*CC])[t] = ((const float2*)g_M)[(size_t)(b0 + half*8 + r)*512 + t];
        #pragma unroll
        for (int r = 0; r < 8; r++) {
            it2[r] = ((const int2*)items)[(size_t)(b0 + half*8 + r)*512 + t];
            dd[r]  = ((const float2*)D)[(size_t)(b0 + half*8 + r)*512 + t];
        }
        __syncthreads();
        #pragma unroll
        for (int r = 0; r < 8; r++) {
            int row = half*8 + r;
            kv[row].x = __expf(5.f*(sbuf[r*CC + it2[r].x] - dd[r].x*inv_mean));
            kv[row].y = __expf(5.f*(sbuf[r*CC + it2[r].y] - dd[r].y*inv_mean));
        }
        __syncthreads();
    }

    const float scaling = (float)BB / 100000.0f;
    float2 cap = ((const float2*)capacities)[t];

    // ---- iteration 1: u1 = 1/rowsum(K), colsum1 partials ----
    #pragma unroll
    for (int r = 0; r < ROWS_S; r++)
        sbuf[r*512 + t] = kv[r].x + kv[r].y;
    __syncthreads();
    {
        float s = 0.f;
        #pragma unroll
        for (int j = 0; j < 16; j++) s += sbuf[w*512 + l + j*32];
        #pragma unroll
        for (int o = 16; o > 0; o >>= 1) s += __shfl_down_sync(0xffffffffu, s, o);
        if (l == 0) su[w] = 1.f / s;
    }
    __syncthreads();
    {
        float2 acc = make_float2(0.f, 0.f);
        #pragma unroll
        for (int r = 0; r < ROWS_S; r++) {
            float u = su[r];
            acc.x += kv[r].x*u; acc.y += kv[r].y*u;
        }
        atomicAdd(&g_cs[1][2*t  ][sb], acc.x);
        atomicAdd(&g_cs[1][2*t+1][sb], acc.y);
    }
    grid_barrier(1);

    // ---- iterations 2..10 ----
    for (int it = 2; it <= NIT; it++) {
        float4 p0 = *(const float4*)&g_cs[it-1][2*t  ][0];
        float4 p1 = *(const float4*)&g_cs[it-1][2*t+1][0];
        float2 vv;
        vv.x = cap.x*scaling / ((p0.x + p0.y) + (p0.z + p0.w));
        vv.y = cap.y*scaling / ((p1.x + p1.y) + (p1.z + p1.w));

        #pragma unroll
        for (int r = 0; r < ROWS_S; r++)
            sbuf[r*512 + t] = kv[r].x*vv.x + kv[r].y*vv.y;
        __syncthreads();
        {
            float s = 0.f;
            #pragma unroll
            for (int j = 0; j < 16; j++) s += sbuf[w*512 + l + j*32];
            #pragma unroll
            for (int o = 16; o > 0; o >>= 1) s += __shfl_down_sync(0xffffffffu, s, o);
            if (l == 0) su[w] = 1.f / s;
        }
        __syncthreads();
        float2 acc = make_float2(0.f, 0.f);
        #pragma unroll
        for (int r = 0; r < ROWS_S; r++) {
            float u = su[r];
            acc.x += kv[r].x*u; acc.y += kv[r].y*u;
        }
        atomicAdd(&g_cs[it][2*t  ][sb], acc.x);
        atomicAdd(&g_cs[it][2*t+1][sb], acc.y);
        grid_barrier(it);
    }

    // ---- final: v10, P = K * u10 (x) v10 (su holds u10) ----
    {
        float4 p0 = *(const float4*)&g_cs[NIT][2*t  ][0];
        float4 p1 = *(const float4*)&g_cs[NIT][2*t+1][0];
        float2 vv;
        vv.x = cap.x*scaling / ((p0.x + p0.y) + (p0.z + p0.w));
        vv.y = cap.y*scaling / ((p1.x + p1.y) + (p1.z + p1.w));
        #pragma unroll
        for (int r = 0; r < ROWS_S; r++) {
            float u = su[r];
            float2 p;
            p.x = kv[r].x*u*vv.x; p.y = kv[r].y*u*vv.y;
            ((float2*)out)[(size_t)(b0 + r)*512 + t] = p;
        }
    }
}

extern "C" void kernel_launch(void* const* d_in, const int* in_sizes, int n_in,
                              void* d_out, int out_size) {
    const int*   users      = (const int*)  d_in[0];
    const int*   items      = (const int*)  d_in[1];
    const float* D          = (const float*)d_in[2];
    const float* capacities = (const float*)d_in[3];
    const float* item_emb   = (const float*)d_in[4];
    const float* user_emb   = (const float*)d_in[5];
    float* out = (float*)d_out;

    k_gemm_mma<<<dim3(CC/64, BB/128), 256>>>(users, user_emb, item_emb, D);
    k_sink<<<NBLK, 512>>>(items, D, capacities, out);
}

// round 12
// speedup vs baseline: 1.5058x; 1.5058x over previous
#include <cuda_runtime.h>
#include <cuda_bf16.h>
#include <cstdint>

#define BB 2048
#define CC 1024
#define FF 128
#define NIT 10
#define NBLK 128              // sink blocks: single wave, barrier-safe
#define ROWS_S (BB/NBLK)      // 16 rows per sink block
#define BANKS 4

// Scratch (no allocs allowed -> device globals)
__device__ float    g_M[BB*CC];             // M[b][j] = ue_b . item_emb[j]
__device__ float    g_cs[NIT+1][BANKS][CC]; // banked colsum partials (bank-MAJOR)
__device__ float    g_sumDp[256];           // per-gemm-block sumD partials (overwrite)
__device__ unsigned g_bar[16];              // grid-barrier counters

// ---------------- tensor-core GEMM + sumD + zeroing --------------------------
__device__ __forceinline__ void ldmx4(uint32_t& r0, uint32_t& r1, uint32_t& r2, uint32_t& r3,
                                      uint32_t addr) {
    asm volatile("ldmatrix.sync.aligned.m8n8.x4.shared.b16 {%0,%1,%2,%3}, [%4];"
                 : "=r"(r0), "=r"(r1), "=r"(r2), "=r"(r3) : "r"(addr));
}

__device__ __forceinline__ uint32_t bf2u(float x, float y) {
    __nv_bfloat162 h = __floats2bfloat162_rn(x, y);
    return *reinterpret_cast<uint32_t*>(&h);
}

__global__ void __launch_bounds__(256) k_gemm_mma(const int* __restrict__ users,
                                                  const float* __restrict__ user_emb,
                                                  const float* __restrict__ item_emb,
                                                  const float* __restrict__ D) {
    __shared__ __align__(16) char smem[49152];   // A: 32KB (128x256B), B: 16KB (64x256B)
    char* sA = smem;
    char* sB = smem + 32768;
    uint32_t sA0 = (uint32_t)__cvta_generic_to_shared(sA);
    uint32_t sB0 = (uint32_t)__cvta_generic_to_shared(sB);

    int t = threadIdx.x;
    int blin = blockIdx.y * gridDim.x + blockIdx.x;
    int r0b = blockIdx.y * 128, c0b = blockIdx.x * 64;

    // ---- D partial loads (consumed at the very end; latency hidden) ----
    float4 dv[8];
    #pragma unroll
    for (int k = 0; k < 8; k++)
        dv[k] = ((const float4*)D)[blin*2048 + t + k*256];

    // ---- zero accumulators ----
    {
        int lin = blin * 256 + t;
        if (lin < (NIT+1)*BANKS*CC) (&g_cs[0][0][0])[lin] = 0.f;
        if (lin < 16) g_bar[lin] = 0u;
    }

    // ---- A tile: gather rows via users, fp32 -> bf16, swizzled smem ----
    #pragma unroll
    for (int l = 0; l < 16; l++) {
        int id = t + l*256;              // 4096 uint4 (128 rows x 32)
        int r = id >> 5, c = id & 31;
        int urow = users[r0b + r];
        uint4 vi = ((const uint4*)(user_emb + (size_t)urow*FF))[c];
        float4 v = *reinterpret_cast<float4*>(&vi);
        uint2 st = make_uint2(bf2u(v.x, v.y), bf2u(v.z, v.w));
        *(uint2*)(sA + r*256 + (((c>>1) ^ (r & 7)) << 4) + ((c & 1) << 3)) = st;
    }
    // ---- B tile: fp32 -> bf16 ----
    #pragma unroll
    for (int l = 0; l < 8; l++) {
        int id = t + l*256;              // 2048 uint4 (64 rows x 32)
        int r = id >> 5, c = id & 31;
        uint4 vi = ((const uint4*)(item_emb + (size_t)(c0b + r)*FF))[c];
        float4 v = *reinterpret_cast<float4*>(&vi);
        uint2 st = make_uint2(bf2u(v.x, v.y), bf2u(v.z, v.w));
        *(uint2*)(sB + r*256 + (((c>>1) ^ (r & 7)) << 4) + ((c & 1) << 3)) = st;
    }
    __syncthreads();

    int wid  = t >> 5, lane = t & 31;
    int wm = wid & 3, wn = wid >> 2;
    int jm = lane >> 3, rr = lane & 7;

    float c[2][4][4];
    #pragma unroll
    for (int mi = 0; mi < 2; mi++)
        #pragma unroll
        for (int nj = 0; nj < 4; nj++)
            #pragma unroll
            for (int e = 0; e < 4; e++) c[mi][nj][e] = 0.f;

    #pragma unroll
    for (int kk = 0; kk < 8; kk++) {
        uint32_t a[2][4];
        #pragma unroll
        for (int mi = 0; mi < 2; mi++) {
            int row = wm*32 + mi*16 + (jm & 1)*8 + rr;
            int ch  = 2*kk + (jm >> 1);
            ldmx4(a[mi][0], a[mi][1], a[mi][2], a[mi][3],
                  sA0 + row*256 + ((ch ^ (row & 7)) << 4));
        }
        uint32_t b[4][2];
        #pragma unroll
        for (int q = 0; q < 2; q++) {
            int row = wn*32 + q*16 + (jm >> 1)*8 + rr;
            int ch  = 2*kk + (jm & 1);
            uint32_t r0_, r1_, r2_, r3_;
            ldmx4(r0_, r1_, r2_, r3_, sB0 + row*256 + ((ch ^ (row & 7)) << 4));
            b[q*2][0] = r0_; b[q*2][1] = r1_;
            b[q*2+1][0] = r2_; b[q*2+1][1] = r3_;
        }
        #pragma unroll
        for (int mi = 0; mi < 2; mi++)
            #pragma unroll
            for (int nj = 0; nj < 4; nj++) {
                asm volatile(
                    "mma.sync.aligned.m16n8k16.row.col.f32.bf16.bf16.f32 "
                    "{%0,%1,%2,%3}, {%4,%5,%6,%7}, {%8,%9}, {%0,%1,%2,%3};"
                    : "+f"(c[mi][nj][0]), "+f"(c[mi][nj][1]),
                      "+f"(c[mi][nj][2]), "+f"(c[mi][nj][3])
                    : "r"(a[mi][0]), "r"(a[mi][1]), "r"(a[mi][2]), "r"(a[mi][3]),
                      "r"(b[nj][0]), "r"(b[nj][1]));
            }
    }

    int g = lane >> 2, tc = lane & 3;
    #pragma unroll
    for (int mi = 0; mi < 2; mi++) {
        int row = r0b + wm*32 + mi*16 + g;
        #pragma unroll
        for (int nj = 0; nj < 4; nj++) {
            int col = c0b + wn*32 + nj*8 + tc*2;
            *(float2*)&g_M[(size_t)row*CC + col]     = make_float2(c[mi][nj][0], c[mi][nj][1]);
            *(float2*)&g_M[(size_t)(row+8)*CC + col] = make_float2(c[mi][nj][2], c[mi][nj][3]);
        }
    }

    // ---- D partial sum -> g_sumDp[blin] (plain overwrite, replay-safe) ----
    float s = 0.f;
    #pragma unroll
    for (int k = 0; k < 8; k++)
        s += (dv[k].x + dv[k].y) + (dv[k].z + dv[k].w);
    __syncthreads();                 // smem A/B reads all done; reuse as reducer
    float* red = (float*)smem;
    red[t] = s; __syncthreads();
    for (int o = 128; o > 0; o >>= 1) { if (t < o) red[t] += red[t+o]; __syncthreads(); }
    if (t == 0) g_sumDp[blin] = red[0];
}

// ------- grid barrier: red.release arrival + ld.acquire spin (no MEMBAR) -------
__device__ __forceinline__ void grid_barrier(int id) {
    __syncthreads();
    if (threadIdx.x == 0) {
        unsigned* p = &g_bar[id];
        asm volatile("red.release.gpu.global.add.u32 [%0], %1;"
                     :: "l"(p), "r"(1u) : "memory");
        unsigned v;
        do {
            asm volatile("ld.acquire.gpu.global.u32 %0, [%1];"
                         : "=r"(v) : "l"(p) : "memory");
        } while (v < (unsigned)NBLK);
    }
    __syncthreads();
}

// ------- fused sink: sumD-reduce + K build + iter1..10 + final P --------------
// R9 sink structure (measured 37.8us), minus phase-0 barrier/D-preload.
// 128 blocks x 512 threads, 16 rows/block; thread t owns cols 2t,2t+1.
__global__ void __launch_bounds__(512, 1)
k_sink(const int* __restrict__ items, const float* __restrict__ D,
       const float* __restrict__ capacities, float* __restrict__ out) {
    __shared__ __align__(16) float sbuf[8*CC];   // 32 KB: mrows stage / rowsum scratch
    __shared__ float su[ROWS_S];
    int t   = threadIdx.x;
    int bid = blockIdx.x;
    int b0  = bid * ROWS_S;
    int sb  = bid & (BANKS-1);
    int w = t >> 5, l = t & 31;

    // ---- sumD: reduce 256 per-gemm-block partials locally (no global barrier) ----
    if (t < 128) sbuf[t] = g_sumDp[t] + g_sumDp[t + 128];
    __syncthreads();
    for (int o = 64; o > 0; o >>= 1) { if (t < o) sbuf[t] += sbuf[t+o]; __syncthreads(); }
    float inv_mean = (float)(BB*CC) / sbuf[0];
    __syncthreads();

    // ---- build K in registers: two 8-row passes over smem-staged M ----
    float2 kv[ROWS_S];
    #pragma unroll
    for (int half = 0; half < 2; half++) {
        #pragma unroll
        for (int r = 0; r < 8; r++)
            ((float2*)&sbuf[r*CC])[t] = ((const float2*)g_M)[(size_t)(b0 + half*8 + r)*512 + t];
        __syncthreads();
        #pragma unroll
        for (int r = 0; r < 8; r++) {
            int row = half*8 + r;
            int2   it2 = ((const int2*)items)[(size_t)(b0+row)*512 + t];
            float2 d2  = ((const float2*)D)[(size_t)(b0+row)*512 + t];
            kv[row].x = __expf(5.f*(sbuf[r*CC + it2.x] - d2.x*inv_mean));
            kv[row].y = __expf(5.f*(sbuf[r*CC + it2.y] - d2.y*inv_mean));
        }
        __syncthreads();
    }

    const float scaling = (float)BB / 100000.0f;
    float2 cap = ((const float2*)capacities)[t];

    // ---- iteration 1: u1 = 1/rowsum(K), colsum1 partials ----
    #pragma unroll
    for (int r = 0; r < ROWS_S; r++)
        sbuf[r*512 + t] = kv[r].x + kv[r].y;
    __syncthreads();
    {
        float s = 0.f;
        #pragma unroll
        for (int j = 0; j < 16; j++) s += sbuf[w*512 + l + j*32];
        #pragma unroll
        for (int o = 16; o > 0; o >>= 1) s += __shfl_down_sync(0xffffffffu, s, o);
        if (l == 0) su[w] = 1.f / s;
    }
    __syncthreads();
    {
        float2 acc = make_float2(0.f, 0.f);
        #pragma unroll
        for (int r = 0; r < ROWS_S; r++) {
            float u = su[r];
            acc.x += kv[r].x*u; acc.y += kv[r].y*u;
        }
        float* cs = &g_cs[1][sb][0];
        atomicAdd(&cs[2*t+0], acc.x);
        atomicAdd(&cs[2*t+1], acc.y);
    }
    grid_barrier(1);

    // ---- iterations 2..10 ----
    for (int it = 2; it <= NIT; it++) {
        float2 c = make_float2(0.f, 0.f);
        #pragma unroll
        for (int s4 = 0; s4 < BANKS; s4++) {
            float2 p = ((const float2*)g_cs[it-1][s4])[t];
            c.x += p.x; c.y += p.y;
        }
        float2 vv;
        vv.x = cap.x*scaling/c.x; vv.y = cap.y*scaling/c.y;

        #pragma unroll
        for (int r = 0; r < ROWS_S; r++)
            sbuf[r*512 + t] = kv[r].x*vv.x + kv[r].y*vv.y;
        __syncthreads();
        {
            float s = 0.f;
            #pragma unroll
            for (int j = 0; j < 16; j++) s += sbuf[w*512 + l + j*32];
            #pragma unroll
            for (int o = 16; o > 0; o >>= 1) s += __shfl_down_sync(0xffffffffu, s, o);
            if (l == 0) su[w] = 1.f / s;
        }
        __syncthreads();
        float2 acc = make_float2(0.f, 0.f);
        #pragma unroll
        for (int r = 0; r < ROWS_S; r++) {
            float u = su[r];
            acc.x += kv[r].x*u; acc.y += kv[r].y*u;
        }
        float* csw = &g_cs[it][sb][0];
        atomicAdd(&csw[2*t+0], acc.x);
        atomicAdd(&csw[2*t+1], acc.y);
        grid_barrier(it);
    }

    // ---- final: v10, P = K * u10 (x) v10 (su holds u10) ----
    {
        float2 c = make_float2(0.f, 0.f);
        #pragma unroll
        for (int s4 = 0; s4 < BANKS; s4++) {
            float2 p = ((const float2*)g_cs[NIT][s4])[t];
            c.x += p.x; c.y += p.y;
        }
        float2 vv;
        vv.x = cap.x*scaling/c.x; vv.y = cap.y*scaling/c.y;
        #pragma unroll
        for (int r = 0; r < ROWS_S; r++) {
            float u = su[r];
            float2 p;
            p.x = kv[r].x*u*vv.x; p.y = kv[r].y*u*vv.y;
            ((float2*)out)[(size_t)(b0 + r)*512 + t] = p;
        }
    }
}

extern "C" void kernel_launch(void* const* d_in, const int* in_sizes, int n_in,
                              void* d_out, int out_size) {
    const int*   users      = (const int*)  d_in[0];
    const int*   items      = (const int*)  d_in[1];
    const float* D          = (const float*)d_in[2];
    const float* capacities = (const float*)d_in[3];
    const float* item_emb   = (const float*)d_in[4];
    const float* user_emb   = (const float*)d_in[5];
    float* out = (float*)d_out;

    k_gemm_mma<<<dim3(CC/64, BB/128), 256>>>(users, user_emb, item_emb, D);
    k_sink<<<NBLK, 512>>>(items, D, capacities, out);
}